// round 13
// baseline (speedup 1.0000x reference)
#include <cuda_runtime.h>
#include <cstdint>
#include <math.h>

#define SEQ   512
#define BATCH 256
#define INS   58
#define HID   256
#define G3    768
#define NCAT  18

#define SCAN_BLOCKS 128
#define BT 32      // batch tile per block
#define HS 16      // hidden strip per block (gates = 3*HS = 48 rows of W_hh)
#define WPAD 260   // padded row stride for smem tiles (floats, 16B aligned)
#define NGROUPS 8  // independent barrier groups (one per batch tile)

// ---------------- device scratch (static allocation only) ----------------
__device__ float g_gx[(size_t)SEQ * BATCH * G3];     // reused per layer
__device__ float g_h0out[(size_t)SEQ * BATCH * HID]; // layer-0 outputs
__device__ float g_hA[BATCH * HID];
__device__ float g_hB[BATCH * HID];
__device__ unsigned g_flags[NGROUPS * 32];           // 16 flags/group in one 64B line

// ---------------- fast gate math -----------------------------------------
__device__ __forceinline__ float fast_sigmoid(float x) {
    return 1.0f / (1.0f + __expf(-x));
}
__device__ __forceinline__ float fast_tanh(float x) {
    return 1.0f - 2.0f / (__expf(2.0f * x) + 1.0f);
}

// ---------------- GEMM: C[M,N] = A[M,K] @ W[N,K]^T + bias[N] --------------
// 128x128 block tile, 8x8 microtile per thread (256 threads).
// K%16==0: float4 LDG + smem transpose (4x fewer L1 wavefronts). else scalar.
__global__ __launch_bounds__(256) void gemm128_bias_kernel(
    const float* __restrict__ A, const float* __restrict__ W,
    const float* __restrict__ bias, float* __restrict__ C,
    int M, int N, int K)
{
    __shared__ float As[16][132];
    __shared__ float Bs[16][132];
    const int tid = threadIdx.x;
    const int tx = tid & 15, ty = tid >> 4;
    const int m0 = blockIdx.y * 128, n0 = blockIdx.x * 128;
    const bool vec = (K % 16 == 0);

    float acc[8][8];
#pragma unroll
    for (int i = 0; i < 8; i++)
#pragma unroll
        for (int j = 0; j < 8; j++) acc[i][j] = 0.f;

    for (int kk = 0; kk < K; kk += 16) {
        if (vec) {
            const int row = tid >> 1;          // 0..127
            const int k4  = (tid & 1) * 8;     // 0 or 8
            const float4 z4 = make_float4(0.f, 0.f, 0.f, 0.f);
            int gm = m0 + row;
            float4 va0 = z4, va1 = z4;
            if (gm < M) {
                va0 = *(const float4*)&A[(size_t)gm * K + kk + k4];
                va1 = *(const float4*)&A[(size_t)gm * K + kk + k4 + 4];
            }
            int gn = n0 + row;
            float4 vb0 = z4, vb1 = z4;
            if (gn < N) {
                vb0 = *(const float4*)&W[(size_t)gn * K + kk + k4];
                vb1 = *(const float4*)&W[(size_t)gn * K + kk + k4 + 4];
            }
            As[k4 + 0][row] = va0.x; As[k4 + 1][row] = va0.y;
            As[k4 + 2][row] = va0.z; As[k4 + 3][row] = va0.w;
            As[k4 + 4][row] = va1.x; As[k4 + 5][row] = va1.y;
            As[k4 + 6][row] = va1.z; As[k4 + 7][row] = va1.w;
            Bs[k4 + 0][row] = vb0.x; Bs[k4 + 1][row] = vb0.y;
            Bs[k4 + 2][row] = vb0.z; Bs[k4 + 3][row] = vb0.w;
            Bs[k4 + 4][row] = vb1.x; Bs[k4 + 5][row] = vb1.y;
            Bs[k4 + 6][row] = vb1.z; Bs[k4 + 7][row] = vb1.w;
        } else {
            const int lr = tid >> 1;
            const int lk = (tid & 1) * 8;
            int gm = m0 + lr;
#pragma unroll
            for (int j = 0; j < 8; j++) {
                int gk = kk + lk + j;
                As[lk + j][lr] = (gm < M && gk < K) ? A[(size_t)gm * K + gk] : 0.f;
            }
            int gn = n0 + lr;
#pragma unroll
            for (int j = 0; j < 8; j++) {
                int gk = kk + lk + j;
                Bs[lk + j][lr] = (gn < N && gk < K) ? W[(size_t)gn * K + gk] : 0.f;
            }
        }
        __syncthreads();
#pragma unroll
        for (int k = 0; k < 16; k++) {
            float a[8], b[8];
            *(float4*)&a[0] = *(const float4*)&As[k][ty * 8];
            *(float4*)&a[4] = *(const float4*)&As[k][ty * 8 + 4];
            *(float4*)&b[0] = *(const float4*)&Bs[k][tx * 8];
            *(float4*)&b[4] = *(const float4*)&Bs[k][tx * 8 + 4];
#pragma unroll
            for (int i = 0; i < 8; i++)
#pragma unroll
                for (int j = 0; j < 8; j++)
                    acc[i][j] = fmaf(a[i], b[j], acc[i][j]);
        }
        __syncthreads();
    }
#pragma unroll
    for (int i = 0; i < 8; i++) {
        int gm = m0 + ty * 8 + i;
        if (gm >= M) continue;
#pragma unroll
        for (int j = 0; j < 8; j++) {
            int gn = n0 + tx * 8 + j;
            if (gn < N) C[(size_t)gm * N + gn] = acc[i][j] + bias[gn];
        }
    }
}

// ---------------- zero initial hidden state + reset barrier flags --------
__global__ void zero_h_kernel() {
    int i = blockIdx.x * 256 + threadIdx.x;
    g_hA[i] = 0.f;
    if (i < NGROUPS * 32) g_flags[i] = 0u;
}

// ---------------- persistent GRU scan over T ------------------------------
// 128 blocks = 8 batch-groups x 16 hidden strips. Flag-array barrier per
// group (no atomics). Half-warp owns its 2 h-rows (syncwarp, 2 k-chunks).
// hprev carried in registers. gx prefetched before the barrier wait.
template <bool STORE_ALL>
__global__ __launch_bounds__(256) void gru_scan_kernel(
    const float* __restrict__ W_hh, const float* __restrict__ b_hh,
    const float* __restrict__ gx, float* __restrict__ h_all)
{
    extern __shared__ float sm[];
    float* Ws  = sm;                       // 48 * WPAD
    float* hs  = Ws + 48 * WPAD;           // BT * WPAD
    float* Gs  = hs + BT * WPAD;           // BT * 52
    float* bsm = Gs + BT * 52;             // 48

    const int tid = threadIdx.x;
    const int bt = blockIdx.x >> 4;        // 0..7   (batch tile / barrier group)
    const int s  = blockIdx.x & 15;        // 0..15  (hidden strip)

    // load persistent W_hh strip: local row lr -> global row (lr/16)*256 + s*16 + lr%16
    for (int i = tid; i < 48 * (HID / 4); i += 256) {
        int lr = i >> 6;
        int c4 = (i & 63) * 4;
        int grow = (lr >> 4) * HID + s * HS + (lr & 15);
        *(float4*)&Ws[lr * WPAD + c4] = *(const float4*)&W_hh[(size_t)grow * HID + c4];
    }
    for (int i = tid; i < 48; i += 256) {
        int grow = (i >> 4) * HID + s * HS + (i & 15);
        bsm[i] = b_hh[grow];
    }

    const int tx = tid & 15, ty = tid >> 4;
    const int lane16 = tid & 15;
    const float* wp0 = &Ws[(3 * tx + 0) * WPAD];
    const float* wp1 = wp0 + WPAD;
    const float* wp2 = wp0 + 2 * WPAD;
    const float* hp0 = &hs[(2 * ty) * WPAD];
    const float* hp1 = hp0 + WPAD;
    float4* d0 = (float4*)(hs + (2 * ty) * WPAD);
    float4* d1 = (float4*)(hs + (2 * ty + 1) * WPAD);

    // gate coordinates: rows row0 = ty and row0+16, column jj = tx
    const int row0 = ty, jj = tx;
    const float* gxp0 = gx + (size_t)(bt * BT + row0) * G3 + s * HS + jj;
    const float* gxp1 = gxp0 + (size_t)16 * G3;
    const size_t hoff0 = (size_t)(bt * BT + row0) * HID + s * HS + jj;
    const size_t hoff1 = hoff0 + (size_t)16 * HID;
    float hprev0 = 0.f, hprev1 = 0.f;

    volatile unsigned* flags = (volatile unsigned*)g_flags;

    for (int t = 0; t < SEQ; t++) {
        // gx prefetch: independent of the barrier, flies during the spin
        const size_t gxo = (size_t)t * BATCH * G3;
        float pr0 = __ldg(gxp0 + gxo);
        float pz0 = __ldg(gxp0 + gxo + 256);
        float pn0 = __ldg(gxp0 + gxo + 512);
        float pr1 = __ldg(gxp1 + gxo);
        float pz1 = __ldg(gxp1 + gxo + 256);
        float pn1 = __ldg(gxp1 + gxo + 512);

        // ---- group barrier: arrive (flag store) + parallel poll ----
        __syncthreads();                       // all prev-step stores/reads done
        if (tid == 0) {
            __threadfence();                   // release h writes
            flags[bt * 32 + s] = (unsigned)(t + 1);
        }
        if (tid < 16) {
            while (flags[bt * 32 + tid] < (unsigned)(t + 1)) { }
            __threadfence();                   // acquire peer h writes
        }
        __syncthreads();

        const float* hsrc = (t & 1) ? g_hB : g_hA;
        float*       hdst = (t & 1) ? g_hA : g_hB;

        // half-warp ty loads its own 2 h rows; chunk1 LDGs hide under chunk0 FMA
        const float4* s0 = (const float4*)(hsrc + (size_t)(bt * BT + 2 * ty) * HID);
        const float4* s1 = (const float4*)(hsrc + (size_t)(bt * BT + 2 * ty + 1) * HID);
        float4 a0 = s0[lane16];       float4 a1 = s0[lane16 + 16];
        float4 b0 = s1[lane16];       float4 b1 = s1[lane16 + 16];
        float4 a2 = s0[lane16 + 32];  float4 a3 = s0[lane16 + 48];
        float4 b2 = s1[lane16 + 32];  float4 b3 = s1[lane16 + 48];
        d0[lane16] = a0; d0[lane16 + 16] = a1;
        d1[lane16] = b0; d1[lane16 + 16] = b1;
        __syncwarp();

        float a00 = 0.f, a01 = 0.f, a02 = 0.f, a10 = 0.f, a11 = 0.f, a12 = 0.f;
#pragma unroll 4
        for (int k = 0; k < HID / 2; k += 4) {
            const float4 h0 = *(const float4*)(hp0 + k);
            const float4 h1 = *(const float4*)(hp1 + k);
            const float4 w0 = *(const float4*)(wp0 + k);
            const float4 w1 = *(const float4*)(wp1 + k);
            const float4 w2 = *(const float4*)(wp2 + k);
            a00 = fmaf(h0.x, w0.x, a00); a00 = fmaf(h0.y, w0.y, a00);
            a00 = fmaf(h0.z, w0.z, a00); a00 = fmaf(h0.w, w0.w, a00);
            a01 = fmaf(h0.x, w1.x, a01); a01 = fmaf(h0.y, w1.y, a01);
            a01 = fmaf(h0.z, w1.z, a01); a01 = fmaf(h0.w, w1.w, a01);
            a02 = fmaf(h0.x, w2.x, a02); a02 = fmaf(h0.y, w2.y, a02);
            a02 = fmaf(h0.z, w2.z, a02); a02 = fmaf(h0.w, w2.w, a02);
            a10 = fmaf(h1.x, w0.x, a10); a10 = fmaf(h1.y, w0.y, a10);
            a10 = fmaf(h1.z, w0.z, a10); a10 = fmaf(h1.w, w0.w, a10);
            a11 = fmaf(h1.x, w1.x, a11); a11 = fmaf(h1.y, w1.y, a11);
            a11 = fmaf(h1.z, w1.z, a11); a11 = fmaf(h1.w, w1.w, a11);
            a12 = fmaf(h1.x, w2.x, a12); a12 = fmaf(h1.y, w2.y, a12);
            a12 = fmaf(h1.z, w2.z, a12); a12 = fmaf(h1.w, w2.w, a12);
        }
        d0[lane16 + 32] = a2; d0[lane16 + 48] = a3;
        d1[lane16 + 32] = b2; d1[lane16 + 48] = b3;
        __syncwarp();
#pragma unroll 4
        for (int k = HID / 2; k < HID; k += 4) {
            const float4 h0 = *(const float4*)(hp0 + k);
            const float4 h1 = *(const float4*)(hp1 + k);
            const float4 w0 = *(const float4*)(wp0 + k);
            const float4 w1 = *(const float4*)(wp1 + k);
            const float4 w2 = *(const float4*)(wp2 + k);
            a00 = fmaf(h0.x, w0.x, a00); a00 = fmaf(h0.y, w0.y, a00);
            a00 = fmaf(h0.z, w0.z, a00); a00 = fmaf(h0.w, w0.w, a00);
            a01 = fmaf(h0.x, w1.x, a01); a01 = fmaf(h0.y, w1.y, a01);
            a01 = fmaf(h0.z, w1.z, a01); a01 = fmaf(h0.w, w1.w, a01);
            a02 = fmaf(h0.x, w2.x, a02); a02 = fmaf(h0.y, w2.y, a02);
            a02 = fmaf(h0.z, w2.z, a02); a02 = fmaf(h0.w, w2.w, a02);
            a10 = fmaf(h1.x, w0.x, a10); a10 = fmaf(h1.y, w0.y, a10);
            a10 = fmaf(h1.z, w0.z, a10); a10 = fmaf(h1.w, w0.w, a10);
            a11 = fmaf(h1.x, w1.x, a11); a11 = fmaf(h1.y, w1.y, a11);
            a11 = fmaf(h1.z, w1.z, a11); a11 = fmaf(h1.w, w1.w, a11);
            a12 = fmaf(h1.x, w2.x, a12); a12 = fmaf(h1.y, w2.y, a12);
            a12 = fmaf(h1.z, w2.z, a12); a12 = fmaf(h1.w, w2.w, a12);
        }
        Gs[(2 * ty + 0) * 52 + 3 * tx + 0] = a00;
        Gs[(2 * ty + 0) * 52 + 3 * tx + 1] = a01;
        Gs[(2 * ty + 0) * 52 + 3 * tx + 2] = a02;
        Gs[(2 * ty + 1) * 52 + 3 * tx + 0] = a10;
        Gs[(2 * ty + 1) * 52 + 3 * tx + 1] = a11;
        Gs[(2 * ty + 1) * 52 + 3 * tx + 2] = a12;
        __syncthreads();

        // gate math + h update; hprev from registers (own output last step)
        {
            float ghr = Gs[row0 * 52 + jj]      + bsm[jj];
            float ghz = Gs[row0 * 52 + 16 + jj] + bsm[16 + jj];
            float ghn = Gs[row0 * 52 + 32 + jj] + bsm[32 + jj];
            float r_ = fast_sigmoid(pr0 + ghr);
            float z_ = fast_sigmoid(pz0 + ghz);
            float n_ = fast_tanh(pn0 + r_ * ghn);
            float hnew = (1.f - z_) * n_ + z_ * hprev0;
            hprev0 = hnew;
            hdst[hoff0] = hnew;
            if (STORE_ALL) h_all[(size_t)t * BATCH * HID + hoff0] = hnew;
        }
        {
            float ghr = Gs[(row0 + 16) * 52 + jj]      + bsm[jj];
            float ghz = Gs[(row0 + 16) * 52 + 16 + jj] + bsm[16 + jj];
            float ghn = Gs[(row0 + 16) * 52 + 32 + jj] + bsm[32 + jj];
            float r_ = fast_sigmoid(pr1 + ghr);
            float z_ = fast_sigmoid(pz1 + ghz);
            float n_ = fast_tanh(pn1 + r_ * ghn);
            float hnew = (1.f - z_) * n_ + z_ * hprev1;
            hprev1 = hnew;
            hdst[hoff1] = hnew;
            if (STORE_ALL) h_all[(size_t)t * BATCH * HID + hoff1] = hnew;
        }
        // top-of-next-iteration __syncthreads closes the step
    }
}

// --------------------------------------------------------------------------
extern "C" void kernel_launch(void* const* d_in, const int* in_sizes, int n_in,
                              void* d_out, int out_size)
{
    const float* x     = (const float*)d_in[0];
    const float* W_ih0 = (const float*)d_in[1];
    const float* W_hh0 = (const float*)d_in[2];
    const float* b_ih0 = (const float*)d_in[3];
    const float* b_hh0 = (const float*)d_in[4];
    const float* W_ih1 = (const float*)d_in[5];
    const float* W_hh1 = (const float*)d_in[6];
    const float* b_ih1 = (const float*)d_in[7];
    const float* b_hh1 = (const float*)d_in[8];
    const float* fc_w  = (const float*)d_in[9];
    const float* fc_b  = (const float*)d_in[10];
    float* out = (float*)d_out;

    float *gx, *h0out, *hA;
    cudaGetSymbolAddress((void**)&gx, g_gx);
    cudaGetSymbolAddress((void**)&h0out, g_h0out);
    cudaGetSymbolAddress((void**)&hA, g_hA);

    const size_t scan_smem =
        (48 * WPAD + BT * WPAD + BT * 52 + 48) * sizeof(float); // ~90 KB
    cudaFuncSetAttribute(gru_scan_kernel<true>,
                         cudaFuncAttributeMaxDynamicSharedMemorySize, (int)scan_smem);
    cudaFuncSetAttribute(gru_scan_kernel<false>,
                         cudaFuncAttributeMaxDynamicSharedMemorySize, (int)scan_smem);

    const int M = SEQ * BATCH;

    // layer 0: gx = x @ W_ih0^T + b_ih0   (K = 58, scalar loader path)
    {
        dim3 grid(G3 / 128, M / 128);
        gemm128_bias_kernel<<<grid, 256>>>(x, W_ih0, b_ih0, gx, M, G3, INS);
    }
    zero_h_kernel<<<BATCH * HID / 256, 256>>>();
    gru_scan_kernel<true><<<SCAN_BLOCKS, 256, scan_smem>>>(W_hh0, b_hh0, gx, h0out);

    // layer 1: gx = h0out @ W_ih1^T + b_ih1   (K = 256, vector loader path)
    {
        dim3 grid(G3 / 128, M / 128);
        gemm128_bias_kernel<<<grid, 256>>>(h0out, W_ih1, b_ih1, gx, M, G3, HID);
    }
    zero_h_kernel<<<BATCH * HID / 256, 256>>>();
    gru_scan_kernel<false><<<SCAN_BLOCKS, 256, scan_smem>>>(W_hh1, b_hh1, gx, nullptr);

    // final FC on last h (SEQ even -> final state lives in g_hA)
    {
        dim3 grid(1, (BATCH + 127) / 128);
        gemm128_bias_kernel<<<grid, 256>>>(hA, fc_w, fc_b, out, BATCH, NCAT, HID);
    }
}